// round 3
// baseline (speedup 1.0000x reference)
#include <cuda_runtime.h>

// Problem constants:
//   features: [B=4, C=256, H=64, W=64] fp32
//   rois:     [R=2048, 5] (batch, x1, y1, x2, y2), SPATIAL_SCALE = 0.25
//   Grid positions h=w={0,7,...,63} are EXACT integers -> bilinear == gather.
//   output:   [R, C, 9, 9] fp32  (maxpool 2x2 s1 of region-of-discard-masked 10x10)

#define BATCH 4
#define NCH   256
#define NPOS  100        // 10x10 grid per channel
#define CHB   128        // channels per block
#define NCHUNK (NCH / CHB)

// Transposed gather: G_t[b][pos][c] = features[b,c,7i,7j], channels contiguous.
__device__ float g_Gt[BATCH * NPOS * NCH];

__global__ void gather_grid_kernel(const float* __restrict__ feat) {
    int idx = blockIdx.x * blockDim.x + threadIdx.x;   // b*100*256 + p*256 + c
    if (idx >= BATCH * NPOS * NCH) return;
    int c  = idx % NCH;
    int bp = idx / NCH;
    int p  = bp % NPOS;
    int b  = bp / NPOS;
    int i = p / 10;
    int j = p % 10;
    g_Gt[idx] = feat[(((b * NCH + c) * 64) + i * 7) * 64 + j * 7];
}

__global__ __launch_bounds__(CHB) void rod_align_max_kernel(
    const float* __restrict__ rois,
    float* __restrict__ out)
{
    __shared__ float sout[CHB * 81];   // 41472 B staged outputs, [c][i][j]

    const int r     = blockIdx.x;      // roi
    const int chunk = blockIdx.y;      // channel chunk
    const int tid   = threadIdx.x;     // channel within chunk

    const float x1 = rois[r * 5 + 1] * 0.25f;
    const float y1 = rois[r * 5 + 2] * 0.25f;
    const float x2 = rois[r * 5 + 3] * 0.25f;
    const float y2 = rois[r * 5 + 4] * 0.25f;
    const int   b  = (int)rois[r * 5 + 0];

    // Column inside-mask (shared across all rows for this thread's channel).
    bool inw[10];
    #pragma unroll
    for (int j = 0; j < 10; j++) {
        float w = (float)j * 7.0f;
        inw[j] = (w >= x1) && (w <= x2);
    }
    bool inh[10];
    #pragma unroll
    for (int i = 0; i < 10; i++) {
        float h = (float)i * 7.0f;
        inh[i] = (h >= y1) && (h <= y2);
    }

    // Base pointer: this thread's channel, position-major with stride NCH.
    const float* gt = g_Gt + b * (NPOS * NCH) + chunk * CHB + tid;

    // Stream rows: load row i (10 coalesced LDG, lane stride = 1 channel),
    // apply region-of-discard mask, vertical max with previous row,
    // horizontal max -> 9 outputs into smem.
    float prev[10], cur[10];
    #pragma unroll
    for (int j = 0; j < 10; j++) {
        float v = gt[j * NCH];
        prev[j] = (inh[0] && inw[j]) ? 0.0f : v;
    }

    float* so = sout + tid * 81;
    #pragma unroll
    for (int i = 1; i < 10; i++) {
        #pragma unroll
        for (int j = 0; j < 10; j++) {
            float v = gt[(i * 10 + j) * NCH];
            cur[j] = (inh[i] && inw[j]) ? 0.0f : v;
        }
        float vm[10];
        #pragma unroll
        for (int j = 0; j < 10; j++)
            vm[j] = fmaxf(prev[j], cur[j]);
        #pragma unroll
        for (int j = 0; j < 9; j++)
            so[(i - 1) * 9 + j] = fmaxf(vm[j], vm[j + 1]);
        #pragma unroll
        for (int j = 0; j < 10; j++)
            prev[j] = cur[j];
    }
    __syncthreads();

    // Coalesced vectorized writeout: 10368 floats = 2592 float4.
    // Block output base = (r*256 + chunk*128)*81 floats -> 16B aligned (x81*4*128).
    float4* o4 = (float4*)(out + (size_t)(r * NCH + chunk * CHB) * 81);
    const float4* s4 = (const float4*)sout;
    #pragma unroll
    for (int k = tid; k < (CHB * 81) / 4; k += CHB)
        o4[k] = s4[k];
}

extern "C" void kernel_launch(void* const* d_in, const int* in_sizes, int n_in,
                              void* d_out, int out_size) {
    const float* features = (const float*)d_in[0];   // [4,256,64,64]
    const float* rois     = (const float*)d_in[1];   // [2048,5]
    float* out = (float*)d_out;                      // [2048,256,9,9]

    const int R = in_sizes[1] / 5;                   // 2048

    int n_g = BATCH * NPOS * NCH;
    gather_grid_kernel<<<(n_g + 255) / 256, 256>>>(features);

    dim3 grid(R, NCHUNK);
    rod_align_max_kernel<<<grid, CHB>>>(rois, out);
}

// round 4
// speedup vs baseline: 1.7669x; 1.7669x over previous
#include <cuda_runtime.h>

// Problem constants:
//   features: [B=4, C=256, H=64, W=64] fp32
//   rois:     [R=2048, 5] (batch, x1, y1, x2, y2), SPATIAL_SCALE = 0.25
//   Grid positions h=w={0,7,...,63} are EXACT integers -> bilinear == gather.
//   output:   [R, C, 9, 9] fp32  (maxpool 2x2 s1 of region-of-discard-masked 10x10)

#define BATCH 4
#define NCH   256
#define NPOS  100        // 10x10 grid per channel
#define CHB   128        // channels per block
#define NCHUNK (NCH / CHB)
#define THREADS 256      // 128 channels x 2 column-halves

// Transposed gather: G_t[b][pos][c] = features[b,c,7i,7j], channels contiguous.
__device__ float g_Gt[BATCH * NPOS * NCH];

__global__ void gather_grid_kernel(const float* __restrict__ feat) {
    int idx = blockIdx.x * blockDim.x + threadIdx.x;   // b*100*256 + p*256 + c
    if (idx >= BATCH * NPOS * NCH) return;
    int c  = idx % NCH;
    int bp = idx / NCH;
    int p  = bp % NPOS;
    int b  = bp / NPOS;
    int i = p / 10;
    int j = p % 10;
    g_Gt[idx] = feat[(((b * NCH + c) * 64) + i * 7) * 64 + j * 7];
}

__global__ __launch_bounds__(THREADS) void rod_align_max_kernel(
    const float* __restrict__ rois,
    float* __restrict__ out)
{
    __shared__ float sout[CHB * 81];   // 41472 B staged outputs, [c][i][j]

    const int r     = blockIdx.x;      // roi
    const int chunk = blockIdx.y;      // channel chunk
    const int tid   = threadIdx.x;
    // Warps 0-3: half=0 (cols 0..5, outputs j=0..4)
    // Warps 4-7: half=1 (cols 4..9, outputs j=4..8)
    // Within each warp: 32 consecutive channels -> perfectly coalesced LDG.
    const int c    = tid & (CHB - 1);  // channel within chunk
    const int half = tid >> 7;
    const int c0   = half * 4;         // first grid column for this half
    const int jb   = half * 4;         // first output column

    const float x1 = rois[r * 5 + 1] * 0.25f;
    const float y1 = rois[r * 5 + 2] * 0.25f;
    const float x2 = rois[r * 5 + 3] * 0.25f;
    const float y2 = rois[r * 5 + 4] * 0.25f;
    const int   b  = (int)rois[r * 5 + 0];

    // Column inside-mask for this half's 6 columns.
    bool inw[6];
    #pragma unroll
    for (int k = 0; k < 6; k++) {
        float w = (float)(c0 + k) * 7.0f;
        inw[k] = (w >= x1) && (w <= x2);
    }

    // This thread's channel base in transposed grid; position stride = NCH.
    const float* gt = g_Gt + b * (NPOS * NCH) + chunk * CHB + c + c0 * NCH;

    // Stream rows: keep only prev/cur 6-wide windows -> low register pressure.
    float prev[6], cur[6];
    {
        bool inh0 = (0.0f >= y1) && (0.0f <= y2);
        #pragma unroll
        for (int k = 0; k < 6; k++) {
            float v = gt[k * NCH];
            prev[k] = (inh0 && inw[k]) ? 0.0f : v;
        }
    }

    float* so = sout + c * 81 + jb;
    #pragma unroll
    for (int i = 1; i < 10; i++) {
        float h = (float)i * 7.0f;
        bool inh = (h >= y1) && (h <= y2);
        #pragma unroll
        for (int k = 0; k < 6; k++) {
            float v = gt[(i * 10) * NCH + k * NCH];
            cur[k] = (inh && inw[k]) ? 0.0f : v;
        }
        float vm[6];
        #pragma unroll
        for (int k = 0; k < 6; k++)
            vm[k] = fmaxf(prev[k], cur[k]);
        // 5 outputs per half; j=4 written identically by both halves.
        #pragma unroll
        for (int k = 0; k < 5; k++)
            so[(i - 1) * 9 + k] = fmaxf(vm[k], vm[k + 1]);
        #pragma unroll
        for (int k = 0; k < 6; k++)
            prev[k] = cur[k];
    }
    __syncthreads();

    // Coalesced vectorized writeout: 10368 floats = 2592 float4.
    float4* o4 = (float4*)(out + (size_t)(r * NCH + chunk * CHB) * 81);
    const float4* s4 = (const float4*)sout;
    for (int k = tid; k < (CHB * 81) / 4; k += THREADS)
        o4[k] = s4[k];
}

extern "C" void kernel_launch(void* const* d_in, const int* in_sizes, int n_in,
                              void* d_out, int out_size) {
    const float* features = (const float*)d_in[0];   // [4,256,64,64]
    const float* rois     = (const float*)d_in[1];   // [2048,5]
    float* out = (float*)d_out;                      // [2048,256,9,9]

    const int R = in_sizes[1] / 5;                   // 2048

    int n_g = BATCH * NPOS * NCH;
    gather_grid_kernel<<<(n_g + 255) / 256, 256>>>(features);

    dim3 grid(R, NCHUNK);
    rod_align_max_kernel<<<grid, THREADS>>>(rois, out);
}

// round 5
// speedup vs baseline: 1.9846x; 1.1232x over previous
#include <cuda_runtime.h>
#include <cstdint>

// Problem constants:
//   features: [B=4, C=256, H=64, W=64] fp32
//   rois:     [R=2048, 5] (batch, x1, y1, x2, y2), SPATIAL_SCALE = 0.25
//   Grid positions h=w={0,7,...,63} are EXACT integers -> bilinear == gather.
//   output:   [R, C, 9, 9] fp32  (maxpool 2x2 s1 of region-of-discard-masked 10x10)

#define BATCH 4
#define NCH   256
#define NPOS  100        // 10x10 grid per channel
#define CHB   128        // channels per block
#define NCHUNK (NCH / CHB)
#define THREADS 256      // 128 channels x 2 column-halves

// Transposed gather: G_t[b][pos][c] = features[b,c,7i,7j], channels contiguous.
__device__ float g_Gt[BATCH * NPOS * NCH];

__global__ void gather_grid_kernel(const float* __restrict__ feat) {
    int idx = blockIdx.x * blockDim.x + threadIdx.x;   // b*100*256 + p*256 + c
    if (idx >= BATCH * NPOS * NCH) return;
    int c  = idx % NCH;
    int bp = idx / NCH;
    int p  = bp % NPOS;
    int b  = bp / NPOS;
    int i = p / 10;
    int j = p % 10;
    g_Gt[idx] = feat[(((b * NCH + c) * 64) + i * 7) * 64 + j * 7];
}

// Compute one column-strip of NCOLS grid columns -> NCOLS-1 output columns.
// gt: thread's base (channel + first column), position stride NCH.
// so: output base in smem for this strip's first output column.
template<int NCOLS>
__device__ __forceinline__ void strip(const float* __restrict__ gt,
                                      float* __restrict__ so,
                                      float x1, float x2, float y1, float y2,
                                      int c0)
{
    bool inw[NCOLS];
    #pragma unroll
    for (int k = 0; k < NCOLS; k++) {
        float w = (float)(c0 + k) * 7.0f;
        inw[k] = (w >= x1) && (w <= x2);
    }

    float prev[NCOLS], cur[NCOLS];
    {
        bool inh0 = (0.0f >= y1) && (0.0f <= y2);
        #pragma unroll
        for (int k = 0; k < NCOLS; k++) {
            float v = gt[k * NCH];
            prev[k] = (inh0 && inw[k]) ? 0.0f : v;
        }
    }
    #pragma unroll
    for (int i = 1; i < 10; i++) {
        float h = (float)i * 7.0f;
        bool inh = (h >= y1) && (h <= y2);
        #pragma unroll
        for (int k = 0; k < NCOLS; k++) {
            float v = gt[(i * 10 + k) * NCH];
            cur[k] = (inh && inw[k]) ? 0.0f : v;
        }
        float vm[NCOLS];
        #pragma unroll
        for (int k = 0; k < NCOLS; k++)
            vm[k] = fmaxf(prev[k], cur[k]);
        #pragma unroll
        for (int k = 0; k < NCOLS - 1; k++)
            so[(i - 1) * 9 + k] = fmaxf(vm[k], vm[k + 1]);
        #pragma unroll
        for (int k = 0; k < NCOLS; k++)
            prev[k] = cur[k];
    }
}

__global__ __launch_bounds__(THREADS) void rod_align_max_kernel(
    const float* __restrict__ rois,
    float* __restrict__ out)
{
    __shared__ __align__(16) float sout[CHB * 81];   // 41472 B staged outputs

    const int r     = blockIdx.x;      // roi
    const int chunk = blockIdx.y;      // channel chunk
    const int tid   = threadIdx.x;
    // Warps 0-3: half=0 -> cols 0..5, outputs j=0..4
    // Warps 4-7: half=1 -> cols 5..9, outputs j=5..8
    // Lanes within a warp = 32 consecutive channels -> perfect 128B LDG.
    const int c    = tid & (CHB - 1);
    const int half = tid >> 7;

    const float x1 = rois[r * 5 + 1] * 0.25f;
    const float y1 = rois[r * 5 + 2] * 0.25f;
    const float x2 = rois[r * 5 + 3] * 0.25f;
    const float y2 = rois[r * 5 + 4] * 0.25f;
    const int   b  = (int)rois[r * 5 + 0];

    const float* gbase = g_Gt + b * (NPOS * NCH) + chunk * CHB + c;
    float* so = sout + c * 81;

    if (half == 0) {
        strip<6>(gbase,           so,     x1, x2, y1, y2, 0);
    } else {
        strip<5>(gbase + 5 * NCH, so + 5, x1, x2, y1, y2, 5);
    }

    // Hand the 41472B contiguous staged block to TMA for the global write.
    asm volatile("fence.proxy.async.shared::cta;" ::: "memory");
    __syncthreads();
    if (tid == 0) {
        uint32_t saddr;
        asm("{ .reg .u64 t; cvta.to.shared.u64 t, %1; cvt.u32.u64 %0, t; }"
            : "=r"(saddr) : "l"(sout));
        float* gdst = out + (size_t)(r * NCH + chunk * CHB) * 81;
        asm volatile(
            "cp.async.bulk.global.shared::cta.bulk_group [%0], [%1], %2;"
            :: "l"(gdst), "r"(saddr), "r"((int)(CHB * 81 * 4)) : "memory");
        asm volatile("cp.async.bulk.commit_group;" ::: "memory");
        // Must not exit the CTA while TMA is still reading our smem.
        asm volatile("cp.async.bulk.wait_group.read 0;" ::: "memory");
    }
}

extern "C" void kernel_launch(void* const* d_in, const int* in_sizes, int n_in,
                              void* d_out, int out_size) {
    const float* features = (const float*)d_in[0];   // [4,256,64,64]
    const float* rois     = (const float*)d_in[1];   // [2048,5]
    float* out = (float*)d_out;                      // [2048,256,9,9]

    const int R = in_sizes[1] / 5;                   // 2048

    int n_g = BATCH * NPOS * NCH;
    gather_grid_kernel<<<(n_g + 255) / 256, 256>>>(features);

    dim3 grid(R, NCHUNK);
    rod_align_max_kernel<<<grid, THREADS>>>(rois, out);
}

// round 6
// speedup vs baseline: 2.0496x; 1.0327x over previous
#include <cuda_runtime.h>
#include <cstdint>

// Problem constants:
//   features: [B=4, C=256, H=64, W=64] fp32
//   rois:     [R=2048, 5] (batch, x1, y1, x2, y2), SPATIAL_SCALE = 0.25
//   Grid positions h=w={0,7,...,63} are EXACT integers -> bilinear == gather.
//   output:   [R, C, 9, 9] fp32  (maxpool 2x2 s1 of region-of-discard-masked 10x10)

#define BATCH 4
#define NCH   256
#define NPOS  100        // 10x10 grid per channel
#define CHB   64         // channels per block
#define NCHUNK (NCH / CHB)
#define THREADS 128      // 64 channels x 2 column-halves

// Transposed gather: G_t[b][pos][c] = features[b,c,7i,7j], channels contiguous.
__device__ float g_Gt[BATCH * NPOS * NCH];

__global__ void gather_grid_kernel(const float* __restrict__ feat) {
    int idx = blockIdx.x * blockDim.x + threadIdx.x;   // b*100*256 + p*256 + c
    if (idx >= BATCH * NPOS * NCH) return;
    int c  = idx % NCH;
    int bp = idx / NCH;
    int p  = bp % NPOS;
    int b  = bp / NPOS;
    int i = p / 10;
    int j = p % 10;
    g_Gt[idx] = feat[(((b * NCH + c) * 64) + i * 7) * 64 + j * 7];
}

// One column-strip of NCOLS grid columns -> NCOLS-1 output columns.
// Loads are branch-predicated: an inside-ROI point is 0 and the predicate is
// warp-uniform (lanes differ only by channel), so masked rows/cols skip the
// L1 wavefront entirely.
template<int NCOLS>
__device__ __forceinline__ void strip(const float* __restrict__ gt,
                                      float* __restrict__ so,
                                      float x1, float x2, float y1, float y2,
                                      int c0)
{
    bool inw[NCOLS];
    #pragma unroll
    for (int k = 0; k < NCOLS; k++) {
        float w = (float)(c0 + k) * 7.0f;
        inw[k] = (w >= x1) && (w <= x2);
    }

    float prev[NCOLS], cur[NCOLS];
    {
        bool inh0 = (0.0f >= y1) && (0.0f <= y2);
        #pragma unroll
        for (int k = 0; k < NCOLS; k++) {
            float v = 0.0f;
            if (!(inh0 && inw[k])) v = __ldg(&gt[k * NCH]);
            prev[k] = v;
        }
    }
    #pragma unroll
    for (int i = 1; i < 10; i++) {
        float h = (float)i * 7.0f;
        bool inh = (h >= y1) && (h <= y2);
        #pragma unroll
        for (int k = 0; k < NCOLS; k++) {
            float v = 0.0f;
            if (!(inh && inw[k])) v = __ldg(&gt[(i * 10 + k) * NCH]);
            cur[k] = v;
        }
        float vm[NCOLS];
        #pragma unroll
        for (int k = 0; k < NCOLS; k++)
            vm[k] = fmaxf(prev[k], cur[k]);
        #pragma unroll
        for (int k = 0; k < NCOLS - 1; k++)
            so[(i - 1) * 9 + k] = fmaxf(vm[k], vm[k + 1]);
        #pragma unroll
        for (int k = 0; k < NCOLS; k++)
            prev[k] = cur[k];
    }
}

__global__ __launch_bounds__(THREADS) void rod_align_max_kernel(
    const float* __restrict__ rois,
    float* __restrict__ out)
{
    __shared__ __align__(16) float sout[CHB * 81];   // 20736 B staged outputs

    const int r     = blockIdx.x;      // roi
    const int chunk = blockIdx.y;      // channel chunk
    const int tid   = threadIdx.x;
    // Warps 0-1: half=0 -> cols 0..5, outputs j=0..4
    // Warps 2-3: half=1 -> cols 5..9, outputs j=5..8
    // Lanes within a warp = 32 consecutive channels -> perfect 128B LDG.
    const int c    = tid & (CHB - 1);
    const int half = tid >> 6;

    const float x1 = rois[r * 5 + 1] * 0.25f;
    const float y1 = rois[r * 5 + 2] * 0.25f;
    const float x2 = rois[r * 5 + 3] * 0.25f;
    const float y2 = rois[r * 5 + 4] * 0.25f;
    const int   b  = (int)rois[r * 5 + 0];

    const float* gbase = g_Gt + b * (NPOS * NCH) + chunk * CHB + c;
    float* so = sout + c * 81;

    if (half == 0) {
        strip<6>(gbase,           so,     x1, x2, y1, y2, 0);
    } else {
        strip<5>(gbase + 5 * NCH, so + 5, x1, x2, y1, y2, 5);
    }

    // Hand the 20736B contiguous staged block to TMA for the global write.
    asm volatile("fence.proxy.async.shared::cta;" ::: "memory");
    __syncthreads();
    if (tid == 0) {
        uint32_t saddr;
        asm("{ .reg .u64 t; cvta.to.shared.u64 t, %1; cvt.u32.u64 %0, t; }"
            : "=r"(saddr) : "l"(sout));
        float* gdst = out + (size_t)(r * NCH + chunk * CHB) * 81;
        asm volatile(
            "cp.async.bulk.global.shared::cta.bulk_group [%0], [%1], %2;"
            :: "l"(gdst), "r"(saddr), "r"((int)(CHB * 81 * 4)) : "memory");
        asm volatile("cp.async.bulk.commit_group;" ::: "memory");
        // Must not exit the CTA while TMA is still reading our smem.
        asm volatile("cp.async.bulk.wait_group.read 0;" ::: "memory");
    }
}

extern "C" void kernel_launch(void* const* d_in, const int* in_sizes, int n_in,
                              void* d_out, int out_size) {
    const float* features = (const float*)d_in[0];   // [4,256,64,64]
    const float* rois     = (const float*)d_in[1];   // [2048,5]
    float* out = (float*)d_out;                      // [2048,256,9,9]

    const int R = in_sizes[1] / 5;                   // 2048

    int n_g = BATCH * NPOS * NCH;
    gather_grid_kernel<<<(n_g + 255) / 256, 256>>>(features);

    dim3 grid(R, NCHUNK);
    rod_align_max_kernel<<<grid, THREADS>>>(rois, out);
}

// round 7
// speedup vs baseline: 2.0515x; 1.0009x over previous
#include <cuda_runtime.h>
#include <cstdint>

// Problem constants:
//   features: [B=4, C=256, H=64, W=64] fp32
//   rois:     [R=2048, 5] (batch, x1, y1, x2, y2), SPATIAL_SCALE = 0.25
//   Grid positions h=w={0,7,...,63} are EXACT integers -> bilinear == gather.
//   output:   [R, C, 9, 9] fp32  (maxpool 2x2 s1 of region-of-discard-masked 10x10)

#define BATCH 4
#define NCH   256
#define NPOS  100        // 10x10 grid per channel
#define CHB   64         // channels per block
#define NCHUNK (NCH / CHB)
#define THREADS 256      // 64 channels x 4 column-strips

// Transposed gather: G_t[b][pos][c] = features[b,c,7i,7j], channels contiguous.
__device__ float g_Gt[BATCH * NPOS * NCH];

__global__ void gather_grid_kernel(const float* __restrict__ feat) {
    int idx = blockIdx.x * blockDim.x + threadIdx.x;   // b*100*256 + p*256 + c
    if (idx >= BATCH * NPOS * NCH) return;
    int c  = idx % NCH;
    int bp = idx / NCH;
    int p  = bp % NPOS;
    int b  = bp / NPOS;
    int i = p / 10;
    int j = p % 10;
    g_Gt[idx] = feat[(((b * NCH + c) * 64) + i * 7) * 64 + j * 7];
}

// One column-strip of NCOLS grid columns -> NCOLS-1 output columns.
// Loads are predicated off when the point is inside the ROI (value would be
// masked to 0); the predicate is warp-uniform so the L1 wavefront is skipped.
template<int NCOLS>
__device__ __forceinline__ void strip(const float* __restrict__ gt,
                                      float* __restrict__ so,
                                      float x1, float x2, float y1, float y2,
                                      int c0)
{
    bool inw[NCOLS];
    #pragma unroll
    for (int k = 0; k < NCOLS; k++) {
        float w = (float)(c0 + k) * 7.0f;
        inw[k] = (w >= x1) && (w <= x2);
    }

    float prev[NCOLS], cur[NCOLS];
    {
        bool inh0 = (0.0f >= y1) && (0.0f <= y2);
        #pragma unroll
        for (int k = 0; k < NCOLS; k++) {
            float v = 0.0f;
            if (!(inh0 && inw[k])) v = __ldg(&gt[k * NCH]);
            prev[k] = v;
        }
    }
    #pragma unroll
    for (int i = 1; i < 10; i++) {
        float h = (float)i * 7.0f;
        bool inh = (h >= y1) && (h <= y2);
        #pragma unroll
        for (int k = 0; k < NCOLS; k++) {
            float v = 0.0f;
            if (!(inh && inw[k])) v = __ldg(&gt[(i * 10 + k) * NCH]);
            cur[k] = v;
        }
        float vm[NCOLS];
        #pragma unroll
        for (int k = 0; k < NCOLS; k++)
            vm[k] = fmaxf(prev[k], cur[k]);
        #pragma unroll
        for (int k = 0; k < NCOLS - 1; k++)
            so[(i - 1) * 9 + k] = fmaxf(vm[k], vm[k + 1]);
        #pragma unroll
        for (int k = 0; k < NCOLS; k++)
            prev[k] = cur[k];
    }
}

__global__ __launch_bounds__(THREADS) void rod_align_max_kernel(
    const float* __restrict__ rois,
    float* __restrict__ out)
{
    __shared__ __align__(16) float sout[CHB * 81];   // 20736 B staged outputs

    const int r     = blockIdx.x;      // roi
    const int chunk = blockIdx.y;      // channel chunk
    const int tid   = threadIdx.x;
    // 4 column-strips; within each strip, warps hold 32 consecutive channels.
    //   q=0: cols 0..3 -> j=0..2     q=1: cols 3..5 -> j=3..4
    //   q=2: cols 5..7 -> j=5..6     q=3: cols 7..9 -> j=7..8
    const int c = tid & (CHB - 1);     // channel within chunk
    const int q = tid >> 6;            // strip id

    const float x1 = rois[r * 5 + 1] * 0.25f;
    const float y1 = rois[r * 5 + 2] * 0.25f;
    const float x2 = rois[r * 5 + 3] * 0.25f;
    const float y2 = rois[r * 5 + 4] * 0.25f;
    const int   b  = (int)rois[r * 5 + 0];

    const float* gbase = g_Gt + b * (NPOS * NCH) + chunk * CHB + c;
    float* so = sout + c * 81;

    if (q == 0)      strip<4>(gbase,           so,     x1, x2, y1, y2, 0);
    else if (q == 1) strip<3>(gbase + 3 * NCH, so + 3, x1, x2, y1, y2, 3);
    else if (q == 2) strip<3>(gbase + 5 * NCH, so + 5, x1, x2, y1, y2, 5);
    else             strip<3>(gbase + 7 * NCH, so + 7, x1, x2, y1, y2, 7);

    // Hand the 20736B contiguous staged block to TMA for the global write.
    asm volatile("fence.proxy.async.shared::cta;" ::: "memory");
    __syncthreads();
    if (tid == 0) {
        uint32_t saddr;
        asm("{ .reg .u64 t; cvta.to.shared.u64 t, %1; cvt.u32.u64 %0, t; }"
            : "=r"(saddr) : "l"(sout));
        float* gdst = out + (size_t)(r * NCH + chunk * CHB) * 81;
        asm volatile(
            "cp.async.bulk.global.shared::cta.bulk_group [%0], [%1], %2;"
            :: "l"(gdst), "r"(saddr), "r"((int)(CHB * 81 * 4)) : "memory");
        asm volatile("cp.async.bulk.commit_group;" ::: "memory");
        // Must not exit the CTA while TMA is still reading our smem.
        asm volatile("cp.async.bulk.wait_group.read 0;" ::: "memory");
    }
}

extern "C" void kernel_launch(void* const* d_in, const int* in_sizes, int n_in,
                              void* d_out, int out_size) {
    const float* features = (const float*)d_in[0];   // [4,256,64,64]
    const float* rois     = (const float*)d_in[1];   // [2048,5]
    float* out = (float*)d_out;                      // [2048,256,9,9]

    const int R = in_sizes[1] / 5;                   // 2048

    int n_g = BATCH * NPOS * NCH;
    gather_grid_kernel<<<(n_g + 255) / 256, 256>>>(features);

    dim3 grid(R, NCHUNK);
    rod_align_max_kernel<<<grid, THREADS>>>(rois, out);
}